// round 8
// baseline (speedup 1.0000x reference)
#include <cuda_runtime.h>

#define N_NODES   100000
#define N_EDGES   1600000
#define N_FEAT    128
#define N_CLASSES 64
#define C4        (N_CLASSES / 4)         // 16 float4 per node row
#define C2        (N_CLASSES / 2)         // 32 float2 per node row
#define NBLK      ((N_NODES + 255) / 256) // 391 scan blocks
#define GEMM_BLKS ((N_NODES + 63) / 64)   // 1563
#define GE_BLKS   ((N_EDGES + 255) / 256) // 6250
#define WT_BLKS   ((N_FEAT * N_CLASSES + 255) / 256) // 32

// ---------------- scratch (device globals; no allocation) ----------------
__device__ int    g_cnt [N_NODES];
__device__ int    g_off [N_NODES];
__device__ int    g_cur [N_NODES];
__device__ int    g_total;
__device__ float  g_dinv[N_NODES];
__device__ __align__(16) int2  g_ew[N_EDGES];            // (src, bits(norm))
__device__ float4 g_wt4[N_FEAT * C4];                    // Wt[k][c], c-contig
__device__ float4 g_y0 [N_NODES * C4];
__device__ float4 g_y1 [N_NODES * C4];
__device__ int    g_is64;

// ---------------- init: zero counts + total + dtype detect ----------------
__global__ void k_init(const int* __restrict__ ei32) {
    int i = blockIdx.x * blockDim.x + threadIdx.x;
    if (i < N_NODES) g_cnt[i] = 0;
    if (i == 0) {
        g_total = 0;
        int ok = 1;
        #pragma unroll
        for (int j = 1; j < 64; j += 2) ok &= (ei32[j] == 0);
        g_is64 = ok;
    }
}

// ---------------- count + W transpose (stitched grid) ----------------
__global__ void k_cw(const void* __restrict__ eiv, const float* __restrict__ W) {
    if (blockIdx.x < GE_BLKS) {
        int e = blockIdx.x * blockDim.x + threadIdx.x;
        if (e >= N_EDGES) return;
        int c;
        if (g_is64) c = (int)((const long long*)eiv)[N_EDGES + e];
        else        c =       ((const int*)      eiv)[N_EDGES + e];
        atomicAdd(&g_cnt[c], 1);
    } else {
        int i = (blockIdx.x - GE_BLKS) * blockDim.x + threadIdx.x;
        if (i >= N_FEAT * N_CLASSES) return;
        int k = i & 127, c = i >> 7;
        ((float*)g_wt4)[k * N_CLASSES + c] = W[c * N_FEAT + k];
    }
}

// ---------------- single-pass offset allocation (block scan + atomic base) ----
// CSR regions need only be disjoint+contiguous per node, not globally ordered,
// so an atomicAdd-allocated block base replaces the 3-launch prefix sum.
__global__ void k_scanA() {
    __shared__ int s[256];
    __shared__ int base;
    int i = blockIdx.x * 256 + threadIdx.x;
    int v = (i < N_NODES) ? g_cnt[i] : 0;
    if (i < N_NODES) g_dinv[i] = rsqrtf((float)v + 1.0f);  // +1 self-loop
    int sum = v;
    s[threadIdx.x] = sum;
    __syncthreads();
    #pragma unroll
    for (int off = 1; off < 256; off <<= 1) {
        int t2 = (threadIdx.x >= off) ? s[threadIdx.x - off] : 0;
        __syncthreads();
        sum += t2;
        s[threadIdx.x] = sum;
        __syncthreads();
    }
    if (threadIdx.x == 255) base = atomicAdd(&g_total, sum);
    __syncthreads();
    if (i < N_NODES) {
        int o = base + sum - v;
        g_off[i] = o;
        g_cur[i] = o;
    }
}

// ---------------- stitched: GEMM (blocks [0,GEMM_BLKS)) + CSR fill ----------------
// GEMM: Y0 = X @ W^T via packed fma.rn.f32x2 (FFMA2 — PTX-only form).
__global__ __launch_bounds__(256) void k_fg(const void* __restrict__ eiv,
                                            const float* __restrict__ X) {
    __shared__ float Xr[64][132];
    if (blockIdx.x < GEMM_BLKS) {
        const int t = threadIdx.x;
        const int node0 = blockIdx.x * 64;

        for (int i = t; i < 64 * 32; i += 256) {
            int n = i >> 5, k4 = i & 31;
            int node = node0 + n;
            float4 v = (node < N_NODES)
                     ? ((const float4*)(X + (size_t)node * N_FEAT))[k4]
                     : make_float4(0.f, 0.f, 0.f, 0.f);
            *(float4*)&Xr[n][k4 * 4] = v;
        }
        __syncthreads();

        const int c16 = t & 15, n16 = t >> 4;
        unsigned long long a01[4], a23[4];
        #pragma unroll
        for (int ni = 0; ni < 4; ni++) { a01[ni] = 0ull; a23[ni] = 0ull; }

        #pragma unroll 4
        for (int k = 0; k < N_FEAT; k++) {
            float4 wv = __ldg(&g_wt4[k * 16 + c16]);
            unsigned long long w01, w23;
            asm("mov.b64 %0, {%1,%2};" : "=l"(w01) : "f"(wv.x), "f"(wv.y));
            asm("mov.b64 %0, {%1,%2};" : "=l"(w23) : "f"(wv.z), "f"(wv.w));
            #pragma unroll
            for (int ni = 0; ni < 4; ni++) {
                float x = Xr[n16 * 4 + ni][k];
                unsigned long long xx;
                asm("mov.b64 %0, {%1,%1};" : "=l"(xx) : "f"(x));
                asm("fma.rn.f32x2 %0, %1, %2, %0;" : "+l"(a01[ni]) : "l"(xx), "l"(w01));
                asm("fma.rn.f32x2 %0, %1, %2, %0;" : "+l"(a23[ni]) : "l"(xx), "l"(w23));
            }
        }

        #pragma unroll
        for (int ni = 0; ni < 4; ni++) {
            int node = node0 + n16 * 4 + ni;
            if (node < N_NODES) {
                float r0, r1, r2, r3;
                asm("mov.b64 {%0,%1}, %2;" : "=f"(r0), "=f"(r1) : "l"(a01[ni]));
                asm("mov.b64 {%0,%1}, %2;" : "=f"(r2), "=f"(r3) : "l"(a23[ni]));
                g_y0[(size_t)node * C4 + c16] = make_float4(r0, r1, r2, r3);
            }
        }
    } else {
        // CSR fill
        int e = (blockIdx.x - GEMM_BLKS) * blockDim.x + threadIdx.x;
        if (e >= N_EDGES) return;
        int r, c;
        if (g_is64) {
            const long long* p = (const long long*)eiv;
            r = (int)p[e]; c = (int)p[N_EDGES + e];
        } else {
            const int* p = (const int*)eiv;
            r = p[e];      c = p[N_EDGES + e];
        }
        int pos = atomicAdd(&g_cur[c], 1);
        if (pos >= 0 && pos < N_EDGES)
            g_ew[pos] = make_int2(r, __float_as_int(g_dinv[r] * g_dinv[c]));
    }
}

// ---------------- propagation hops: one node per warp, float2 per lane ----------
__device__ __forceinline__ float2 hop_accum2(const float2* __restrict__ in,
                                             int node, int lane, float2 acc) {
    int j   = g_off[node];
    int end = j + g_cnt[node];
    if (end > N_EDGES) end = N_EDGES;   // defensive

    for (; j + 3 < end; j += 4) {
        int2 e0 = __ldg(&g_ew[j]);      // 32-lane broadcast
        int2 e1 = __ldg(&g_ew[j + 1]);
        int2 e2 = __ldg(&g_ew[j + 2]);
        int2 e3 = __ldg(&g_ew[j + 3]);
        float2 u0 = __ldg(&in[(size_t)e0.x * C2 + lane]);
        float2 u1 = __ldg(&in[(size_t)e1.x * C2 + lane]);
        float2 u2 = __ldg(&in[(size_t)e2.x * C2 + lane]);
        float2 u3 = __ldg(&in[(size_t)e3.x * C2 + lane]);
        float w0 = __int_as_float(e0.y), w1 = __int_as_float(e1.y);
        float w2 = __int_as_float(e2.y), w3 = __int_as_float(e3.y);
        acc.x = fmaf(w0, u0.x, acc.x); acc.y = fmaf(w0, u0.y, acc.y);
        acc.x = fmaf(w1, u1.x, acc.x); acc.y = fmaf(w1, u1.y, acc.y);
        acc.x = fmaf(w2, u2.x, acc.x); acc.y = fmaf(w2, u2.y, acc.y);
        acc.x = fmaf(w3, u3.x, acc.x); acc.y = fmaf(w3, u3.y, acc.y);
    }
    for (; j < end; j++) {
        int2 e0 = __ldg(&g_ew[j]);
        float w0 = __int_as_float(e0.y);
        float2 u0 = __ldg(&in[(size_t)e0.x * C2 + lane]);
        acc.x = fmaf(w0, u0.x, acc.x); acc.y = fmaf(w0, u0.y, acc.y);
    }
    return acc;
}

__global__ void k_hop1() {   // g_y1 = P(g_y0)
    int t = blockIdx.x * blockDim.x + threadIdx.x;
    int node = t >> 5;
    if (node >= N_NODES) return;
    int lane = t & 31;
    const float2* in = (const float2*)g_y0;

    float dv = g_dinv[node];
    float s = dv * dv;
    float2 v = in[(size_t)node * C2 + lane];
    float2 acc = make_float2(v.x * s, v.y * s);
    acc = hop_accum2(in, node, lane, acc);
    ((float2*)g_y1)[(size_t)node * C2 + lane] = acc;
}

__global__ void k_hop2(float2* __restrict__ out,
                       const float2* __restrict__ bias) {  // out = P(g_y1) + b
    int t = blockIdx.x * blockDim.x + threadIdx.x;
    int node = t >> 5;
    if (node >= N_NODES) return;
    int lane = t & 31;
    const float2* in = (const float2*)g_y1;

    float dv = g_dinv[node];
    float s = dv * dv;
    float2 v  = in[(size_t)node * C2 + lane];
    float2 bb = __ldg(&bias[lane]);
    float2 acc = make_float2(fmaf(v.x, s, bb.x), fmaf(v.y, s, bb.y));
    acc = hop_accum2(in, node, lane, acc);
    out[(size_t)node * C2 + lane] = acc;
}

// ---------------- launch ----------------
extern "C" void kernel_launch(void* const* d_in, const int* in_sizes, int n_in,
                              void* d_out, int out_size) {
    const float* X  = (const float*)d_in[0];
    const void*  EI =               d_in[1];
    const float* W  = (const float*)d_in[2];
    const float* B  = (const float*)d_in[3];

    const int TB = 256;
    const int gN = (N_NODES + TB - 1) / TB;

    k_init <<<gN, TB>>>((const int*)EI);
    k_cw   <<<GE_BLKS + WT_BLKS, TB>>>(EI, W);
    k_scanA<<<NBLK, 256>>>();
    k_fg   <<<GEMM_BLKS + GE_BLKS, TB>>>(EI, X);

    int gH = (N_NODES * 32 + TB - 1) / TB;   // one warp per node
    k_hop1<<<gH, TB>>>();
    k_hop2<<<gH, TB>>>((float2*)d_out, (const float2*)B);
}

// round 9
// speedup vs baseline: 1.1457x; 1.1457x over previous
#include <cuda_runtime.h>
#include <string.h>

#define N_NODES   100000
#define N_EDGES   1600000
#define N_FEAT    128
#define N_CLASSES 64
#define C4        (N_CLASSES / 4)         // 16 float4 per node row
#define NBLK      ((N_NODES + 255) / 256) // 391 scan blocks
#define GEMM_BLKS ((N_NODES + 63) / 64)   // 1563
#define GE_BLKS   ((N_EDGES + 255) / 256) // 6250
#define WP_BLKS   ((N_FEAT * N_CLASSES + 255) / 256) // 32 permute blocks

// ---------------- scratch (device globals; no allocation) ----------------
__device__ int    g_cnt [N_NODES];
__device__ int    g_off [N_NODES];
__device__ int    g_cur [N_NODES];
__device__ int    g_total;
__device__ float  g_dinv[N_NODES];
__device__ int    g_csr [N_EDGES];        // src only (weights via z-substitution)
__device__ float4 g_wt4 [N_FEAT * C4];    // Wkc[k4][ci][c16] = W[4*c16+ci][4*k4..+3]
__device__ float4 g_z0  [N_NODES * C4];   // dinv * (X @ W^T)
__device__ float4 g_z1  [N_NODES * C4];   // dinv * y1
__device__ int    g_is64;

// ---------------- init: zero counts + total + dtype detect ----------------
__global__ void k_init(const int* __restrict__ ei32) {
    int i = blockIdx.x * blockDim.x + threadIdx.x;
    if (i < N_NODES) g_cnt[i] = 0;
    if (i == 0) {
        g_total = 0;
        int ok = 1;
        #pragma unroll
        for (int j = 1; j < 64; j += 2) ok &= (ei32[j] == 0);
        g_is64 = ok;
    }
}

// ---------------- count + W permute (stitched grid) ----------------
// Permute: g_wt4[k4*64 + ci*16 + c16].m = W[(4*c16+ci)*128 + 4*k4 + m]
__global__ void k_cw(const void* __restrict__ eiv, const float* __restrict__ W) {
    if (blockIdx.x < GE_BLKS) {
        int e = blockIdx.x * blockDim.x + threadIdx.x;
        if (e >= N_EDGES) return;
        int c;
        if (g_is64) c = (int)((const long long*)eiv)[N_EDGES + e];
        else        c =       ((const int*)      eiv)[N_EDGES + e];
        atomicAdd(&g_cnt[c], 1);
    } else {
        int o = (blockIdx.x - GE_BLKS) * blockDim.x + threadIdx.x;
        if (o >= N_FEAT * N_CLASSES) return;
        int m   = o & 3;
        int c16 = (o >> 2) & 15;
        int ci  = (o >> 6) & 3;
        int k4  = o >> 8;
        ((float*)g_wt4)[o] = W[(4 * c16 + ci) * N_FEAT + 4 * k4 + m];
    }
}

// ---------------- single-pass offset allocation (block scan + atomic base) ----
__global__ void k_scanA() {
    __shared__ int s[256];
    __shared__ int base;
    int i = blockIdx.x * 256 + threadIdx.x;
    int v = (i < N_NODES) ? g_cnt[i] : 0;
    if (i < N_NODES) g_dinv[i] = rsqrtf((float)v + 1.0f);  // +1 self-loop
    int sum = v;
    s[threadIdx.x] = sum;
    __syncthreads();
    #pragma unroll
    for (int off = 1; off < 256; off <<= 1) {
        int t2 = (threadIdx.x >= off) ? s[threadIdx.x - off] : 0;
        __syncthreads();
        sum += t2;
        s[threadIdx.x] = sum;
        __syncthreads();
    }
    if (threadIdx.x == 255) base = atomicAdd(&g_total, sum);
    __syncthreads();
    if (i < N_NODES) {
        int o = base + sum - v;
        g_off[i] = o;
        g_cur[i] = o;
    }
}

// helper: FFMA2 on packed f32x2
__device__ __forceinline__ void ffma2(unsigned long long& acc,
                                      unsigned long long a, unsigned long long b) {
    asm("fma.rn.f32x2 %0, %1, %2, %0;" : "+l"(acc) : "l"(a), "l"(b));
}

// ---------------- stitched: GEMM (blocks [0,GEMM_BLKS)) + CSR fill ----------------
// GEMM: z0 = dinv * (X @ W^T). k-pair packed FFMA2, zero packing movs.
// Thread = 4 classes (c = 4*c16..+3) x 4 nodes (n16*4..+3); 64 nodes/block.
__global__ __launch_bounds__(256) void k_fg(const void* __restrict__ eiv,
                                            const float* __restrict__ X) {
    __shared__ float Xr[64][132];
    if (blockIdx.x < GEMM_BLKS) {
        const int t = threadIdx.x;
        const int node0 = blockIdx.x * 64;

        for (int i = t; i < 64 * 32; i += 256) {
            int n = i >> 5, k4 = i & 31;
            int node = node0 + n;
            float4 v = (node < N_NODES)
                     ? ((const float4*)(X + (size_t)node * N_FEAT))[k4]
                     : make_float4(0.f, 0.f, 0.f, 0.f);
            *(float4*)&Xr[n][k4 * 4] = v;
        }
        __syncthreads();

        const int c16 = t & 15, n16 = t >> 4;
        unsigned long long acc[4][4];   // [ni][ci], even/odd-k partial sums
        #pragma unroll
        for (int ni = 0; ni < 4; ni++)
            #pragma unroll
            for (int ci = 0; ci < 4; ci++) acc[ni][ci] = 0ull;

        #pragma unroll 8
        for (int k4 = 0; k4 < 32; k4++) {
            ulonglong2 xu[4];
            #pragma unroll
            for (int ni = 0; ni < 4; ni++) {
                float4 xv = *(const float4*)&Xr[n16 * 4 + ni][k4 * 4];
                memcpy(&xu[ni], &xv, 16);
            }
            #pragma unroll
            for (int ci = 0; ci < 4; ci++) {
                float4 wv = __ldg(&g_wt4[k4 * 64 + ci * 16 + c16]);
                ulonglong2 wu;
                memcpy(&wu, &wv, 16);
                #pragma unroll
                for (int ni = 0; ni < 4; ni++) {
                    ffma2(acc[ni][ci], xu[ni].x, wu.x);
                    ffma2(acc[ni][ci], xu[ni].y, wu.y);
                }
            }
        }

        #pragma unroll
        for (int ni = 0; ni < 4; ni++) {
            int node = node0 + n16 * 4 + ni;
            if (node < N_NODES) {
                float dv = __ldg(&g_dinv[node]);
                float4 r;
                float lo, hi;
                asm("mov.b64 {%0,%1}, %2;" : "=f"(lo), "=f"(hi) : "l"(acc[ni][0]));
                r.x = (lo + hi) * dv;
                asm("mov.b64 {%0,%1}, %2;" : "=f"(lo), "=f"(hi) : "l"(acc[ni][1]));
                r.y = (lo + hi) * dv;
                asm("mov.b64 {%0,%1}, %2;" : "=f"(lo), "=f"(hi) : "l"(acc[ni][2]));
                r.z = (lo + hi) * dv;
                asm("mov.b64 {%0,%1}, %2;" : "=f"(lo), "=f"(hi) : "l"(acc[ni][3]));
                r.w = (lo + hi) * dv;
                g_z0[(size_t)node * C4 + c16] = r;
            }
        }
    } else {
        // CSR fill: src index only
        int e = (blockIdx.x - GEMM_BLKS) * blockDim.x + threadIdx.x;
        if (e >= N_EDGES) return;
        int r, c;
        if (g_is64) {
            const long long* p = (const long long*)eiv;
            r = (int)p[e]; c = (int)p[N_EDGES + e];
        } else {
            const int* p = (const int*)eiv;
            r = p[e];      c = p[N_EDGES + e];
        }
        int pos = atomicAdd(&g_cur[c], 1);
        if (pos >= 0 && pos < N_EDGES)
            g_csr[pos] = r;
    }
}

// ---------------- propagation hops: 16 lanes/node, float4, z-form ----------------
__device__ __forceinline__ float4 hop_sum(const float4* __restrict__ in,
                                          int node, int lane, float4 acc) {
    int j   = g_off[node];
    int end = j + g_cnt[node];
    if (end > N_EDGES) end = N_EDGES;   // defensive

    for (; j + 3 < end; j += 4) {
        int s0 = __ldg(&g_csr[j]);
        int s1 = __ldg(&g_csr[j + 1]);
        int s2 = __ldg(&g_csr[j + 2]);
        int s3 = __ldg(&g_csr[j + 3]);
        float4 u0 = __ldg(&in[(size_t)s0 * C4 + lane]);
        float4 u1 = __ldg(&in[(size_t)s1 * C4 + lane]);
        float4 u2 = __ldg(&in[(size_t)s2 * C4 + lane]);
        float4 u3 = __ldg(&in[(size_t)s3 * C4 + lane]);
        acc.x += u0.x + u1.x; acc.y += u0.y + u1.y;
        acc.z += u0.z + u1.z; acc.w += u0.w + u1.w;
        acc.x += u2.x + u3.x; acc.y += u2.y + u3.y;
        acc.z += u2.z + u3.z; acc.w += u2.w + u3.w;
    }
    for (; j < end; j++) {
        int s0 = __ldg(&g_csr[j]);
        float4 u0 = __ldg(&in[(size_t)s0 * C4 + lane]);
        acc.x += u0.x; acc.y += u0.y; acc.z += u0.z; acc.w += u0.w;
    }
    return acc;
}

__global__ void k_hop1() {   // g_z1 = dinv^2 * (z0 + sum z0[src])
    int t = blockIdx.x * blockDim.x + threadIdx.x;
    int node = t >> 4;
    if (node >= N_NODES) return;
    int lane = t & 15;

    float4 acc = g_z0[(size_t)node * C4 + lane];   // self term
    acc = hop_sum(g_z0, node, lane, acc);
    float dv = g_dinv[node];
    float s = dv * dv;
    acc.x *= s; acc.y *= s; acc.z *= s; acc.w *= s;
    g_z1[(size_t)node * C4 + lane] = acc;
}

__global__ void k_hop2(float4* __restrict__ out,
                       const float4* __restrict__ bias) {  // out = dinv*(z1+sum) + b
    int t = blockIdx.x * blockDim.x + threadIdx.x;
    int node = t >> 4;
    if (node >= N_NODES) return;
    int lane = t & 15;

    float4 acc = g_z1[(size_t)node * C4 + lane];   // self term
    acc = hop_sum(g_z1, node, lane, acc);
    float dv = g_dinv[node];
    float4 bb = __ldg(&bias[lane]);
    out[(size_t)node * C4 + lane] =
        make_float4(fmaf(acc.x, dv, bb.x), fmaf(acc.y, dv, bb.y),
                    fmaf(acc.z, dv, bb.z), fmaf(acc.w, dv, bb.w));
}

// ---------------- launch ----------------
extern "C" void kernel_launch(void* const* d_in, const int* in_sizes, int n_in,
                              void* d_out, int out_size) {
    const float* X  = (const float*)d_in[0];
    const void*  EI =               d_in[1];
    const float* W  = (const float*)d_in[2];
    const float* B  = (const float*)d_in[3];

    const int TB = 256;
    const int gN = (N_NODES + TB - 1) / TB;

    k_init <<<gN, TB>>>((const int*)EI);
    k_cw   <<<GE_BLKS + WP_BLKS, TB>>>(EI, W);
    k_scanA<<<NBLK, 256>>>();
    k_fg   <<<GEMM_BLKS + GE_BLKS, TB>>>(EI, X);

    int gH = (N_NODES * 16 + TB - 1) / TB;   // 16 lanes per node
    k_hop1<<<gH, TB>>>();
    k_hop2<<<gH, TB>>>((float4*)d_out, (const float4*)B);
}

// round 11
// speedup vs baseline: 1.1602x; 1.0126x over previous
#include <cuda_runtime.h>
#include <stdint.h>

#define N_NODES   100000
#define N_EDGES   1600000
#define N_FEAT    128
#define N_CLASSES 64
#define C4        (N_CLASSES / 4)         // 16 float4 per node row
#define NBLK      ((N_NODES + 255) / 256) // 391 scan blocks
#define GE_BLKS   ((N_EDGES + 255) / 256) // 6250 (256-thr count blocks)
#define WS_BLKS   ((N_FEAT * N_CLASSES + 255) / 256) // 32 W-pack blocks
#define MM_BLKS   ((N_NODES + 63) / 64)   // 1563 GEMM blocks (64 nodes each)
#define FI_BLKS   ((N_EDGES + 127) / 128) // 12500 fill blocks (128 thr)

// ---------------- scratch (device globals; no allocation) ----------------
__device__ int    g_cnt [N_NODES];
__device__ int    g_deg [N_NODES];
__device__ int    g_off [N_NODES];
__device__ int    g_cur [N_NODES];
__device__ int    g_total;
__device__ float  g_dinv[N_NODES];
__device__ int    g_csr [N_EDGES];            // src only (weights via z-substitution)
// W in B-fragment order: [kt(16)][nt(8)][lane(32)] x float4{bh0,bh1,bl0,bl1}
__device__ __align__(16) float g_wf[16 * 8 * 32 * 4];
__device__ float4 g_z0  [N_NODES * C4];       // dinv * (X @ W^T)
__device__ float4 g_z1  [N_NODES * C4];
__device__ int    g_is64;

// ---------------- helpers ----------------
__device__ __forceinline__ uint32_t f2tf32(float x) {
    uint32_t r;
    asm("cvt.rna.tf32.f32 %0, %1;" : "=r"(r) : "f"(x));
    return r;
}
__device__ __forceinline__ void mma_tf32(float* c,
                                         uint32_t a0, uint32_t a1, uint32_t a2, uint32_t a3,
                                         uint32_t b0, uint32_t b1) {
    asm volatile(
        "mma.sync.aligned.m16n8k8.row.col.f32.tf32.tf32.f32 "
        "{%0,%1,%2,%3}, {%4,%5,%6,%7}, {%8,%9}, {%0,%1,%2,%3};"
        : "+f"(c[0]), "+f"(c[1]), "+f"(c[2]), "+f"(c[3])
        : "r"(a0), "r"(a1), "r"(a2), "r"(a3), "r"(b0), "r"(b1));
}

// ---------------- init: dtype detect + total reset ----------------
__global__ void k_init(const int* __restrict__ ei32) {
    if (threadIdx.x == 0) {
        g_total = 0;
        int ok = 1;
        #pragma unroll
        for (int j = 1; j < 64; j += 2) ok &= (ei32[j] == 0);
        g_is64 = ok;
    }
}

// ---------------- count + W split/pack (stitched grid) ----------------
// Pack W[c][k] into B-fragment order with tf32 hi/lo split.
// Fragment (kt,nt): b0 = W[nt*8 + lane/4][kt*8 + lane%4], b1 = same, k+4.
__global__ void k_cw(const void* __restrict__ eiv, const float* __restrict__ W) {
    if (blockIdx.x < GE_BLKS) {
        int e = blockIdx.x * blockDim.x + threadIdx.x;
        if (e >= N_EDGES) return;
        int c;
        if (g_is64) c = (int)((const long long*)eiv)[N_EDGES + e];
        else        c =       ((const int*)      eiv)[N_EDGES + e];
        atomicAdd(&g_cnt[c], 1);
    } else {
        int o = (blockIdx.x - GE_BLKS) * blockDim.x + threadIdx.x;
        if (o >= N_FEAT * N_CLASSES) return;
        int c = o >> 7, k = o & 127;
        float w = W[o];
        uint32_t hi = f2tf32(w);
        uint32_t lo = f2tf32(w - __uint_as_float(hi));
        int kt = k >> 3, kc = k & 7, nt = c >> 3;
        int lane = (c & 7) * 4 + (kc & 3);
        int slot = kc >> 2;                       // 0 -> b0, 1 -> b1
        int idx  = ((kt * 8 + nt) * 32 + lane) * 4;
        g_wf[idx + slot]     = __uint_as_float(hi);
        g_wf[idx + 2 + slot] = __uint_as_float(lo);
    }
}

// ---------------- offset allocation + dinv + deg snapshot + count reset ----------
__global__ void k_scanA() {
    __shared__ int s[256];
    __shared__ int base;
    int i = blockIdx.x * 256 + threadIdx.x;
    int v = (i < N_NODES) ? g_cnt[i] : 0;
    if (i < N_NODES) {
        g_cnt[i] = 0;                        // reset for next replay
        g_deg[i] = v;
        g_dinv[i] = rsqrtf((float)v + 1.0f); // +1 self-loop
    }
    int sum = v;
    s[threadIdx.x] = sum;
    __syncthreads();
    #pragma unroll
    for (int off = 1; off < 256; off <<= 1) {
        int t2 = (threadIdx.x >= off) ? s[threadIdx.x - off] : 0;
        __syncthreads();
        sum += t2;
        s[threadIdx.x] = sum;
        __syncthreads();
    }
    if (threadIdx.x == 255) base = atomicAdd(&g_total, sum);
    __syncthreads();
    if (i < N_NODES) {
        int o = base + sum - v;
        g_off[i] = o;
        g_cur[i] = o;
    }
}

// ---------------- stitched: 3xTF32 mma GEMM + CSR fill ----------------
// GEMM: z0 = dinv * (X @ W^T). Warp = 16 nodes x 64 classes; block = 64 nodes.
__global__ __launch_bounds__(128) void k_mf(const void* __restrict__ eiv,
                                            const float* __restrict__ X) {
    __shared__ float Xs[64][132];
    if (blockIdx.x < MM_BLKS) {
        const int tid = threadIdx.x, w = tid >> 5, lane = tid & 31;
        const int node0 = blockIdx.x * 64;

        for (int i = tid; i < 64 * 32; i += 128) {
            int n = i >> 5, q = i & 31;
            int node = node0 + n;
            float4 v = (node < N_NODES)
                     ? __ldg((const float4*)(X + (size_t)node * N_FEAT) + q)
                     : make_float4(0.f, 0.f, 0.f, 0.f);
            *(float4*)&Xs[n][q * 4] = v;
        }
        __syncthreads();

        float acc[8][4];
        #pragma unroll
        for (int nt = 0; nt < 8; nt++)
            #pragma unroll
            for (int i = 0; i < 4; i++) acc[nt][i] = 0.f;

        const int r0 = w * 16 + (lane >> 2);     // rows r0, r0+8 of block tile
        const int kc = lane & 3;
        const float4* wf = (const float4*)g_wf;

        #pragma unroll
        for (int kt = 0; kt < 16; kt++) {
            float x0 = Xs[r0][kt * 8 + kc];
            float x1 = Xs[r0 + 8][kt * 8 + kc];
            float x2 = Xs[r0][kt * 8 + kc + 4];
            float x3 = Xs[r0 + 8][kt * 8 + kc + 4];
            uint32_t ah0 = f2tf32(x0), ah1 = f2tf32(x1);
            uint32_t ah2 = f2tf32(x2), ah3 = f2tf32(x3);
            uint32_t al0 = f2tf32(x0 - __uint_as_float(ah0));
            uint32_t al1 = f2tf32(x1 - __uint_as_float(ah1));
            uint32_t al2 = f2tf32(x2 - __uint_as_float(ah2));
            uint32_t al3 = f2tf32(x3 - __uint_as_float(ah3));
            #pragma unroll
            for (int nt = 0; nt < 8; nt++) {
                float4 b = __ldg(&wf[(kt * 8 + nt) * 32 + lane]);
                uint32_t bh0 = __float_as_uint(b.x), bh1 = __float_as_uint(b.y);
                uint32_t bl0 = __float_as_uint(b.z), bl1 = __float_as_uint(b.w);
                mma_tf32(acc[nt], ah0, ah1, ah2, ah3, bh0, bh1);  // hi*hi
                mma_tf32(acc[nt], ah0, ah1, ah2, ah3, bl0, bl1);  // hi*lo
                mma_tf32(acc[nt], al0, al1, al2, al3, bh0, bh1);  // lo*hi
            }
        }

        // epilogue: scale by dinv, store. c0,c1 -> row r0; c2,c3 -> row r0+8.
        int nodeA = node0 + r0, nodeB = nodeA + 8;
        float dA = (nodeA < N_NODES) ? g_dinv[nodeA] : 0.f;
        float dB = (nodeB < N_NODES) ? g_dinv[nodeB] : 0.f;
        float* z = (float*)g_z0;
        #pragma unroll
        for (int nt = 0; nt < 8; nt++) {
            int col = nt * 8 + kc * 2;
            if (nodeA < N_NODES)
                *(float2*)&z[(size_t)nodeA * N_CLASSES + col] =
                    make_float2(acc[nt][0] * dA, acc[nt][1] * dA);
            if (nodeB < N_NODES)
                *(float2*)&z[(size_t)nodeB * N_CLASSES + col] =
                    make_float2(acc[nt][2] * dB, acc[nt][3] * dB);
        }
    } else {
        // CSR fill: src index only
        int e = (blockIdx.x - MM_BLKS) * 128 + threadIdx.x;
        if (e >= N_EDGES) return;
        int r, c;
        if (g_is64) {
            const long long* p = (const long long*)eiv;
            r = (int)p[e]; c = (int)p[N_EDGES + e];
        } else {
            const int* p = (const int*)eiv;
            r = p[e];      c = p[N_EDGES + e];
        }
        int pos = atomicAdd(&g_cur[c], 1);
        if (pos >= 0 && pos < N_EDGES)
            g_csr[pos] = r;
    }
}

// ---------------- propagation hops: 16 lanes/node, float4, z-form ----------------
__device__ __forceinline__ float4 hop_sum(const float4* __restrict__ in,
                                          int node, int lane, float4 acc) {
    int j   = g_off[node];
    int end = j + g_deg[node];
    if (end > N_EDGES) end = N_EDGES;   // defensive

    for (; j + 3 < end; j += 4) {
        int s0 = __ldg(&g_csr[j]);
        int s1 = __ldg(&g_csr[j + 1]);
        int s2 = __ldg(&g_csr[j + 2]);
        int s3 = __ldg(&g_csr[j + 3]);
        float4 u0 = __ldg(&in[(size_t)s0 * C4 + lane]);
        float4 u1 = __ldg(&in[(size_t)s1 * C4 + lane]);
        float4 u2 = __ldg(&in[(size_t)s2 * C4 + lane]);
        float4 u3 = __ldg(&in[(size_t)s3 * C4 + lane]);
        acc.x += u0.x + u1.x; acc.y += u0.y + u1.y;
        acc.z += u0.z + u1.z; acc.w += u0.w + u1.w;
        acc.x += u2.x + u3.x; acc.y += u2.y + u3.y;
        acc.z += u2.z + u3.z; acc.w += u2.w + u3.w;
    }
    for (; j < end; j++) {
        int s0 = __ldg(&g_csr[j]);
        float4 u0 = __ldg(&in[(size_t)s0 * C4 + lane]);
        acc.x += u0.x; acc.y += u0.y; acc.z += u0.z; acc.w += u0.w;
    }
    return acc;
}

__global__ void k_hop1() {   // g_z1 = dinv^2 * (z0 + sum z0[src])
    int t = blockIdx.x * blockDim.x + threadIdx.x;
    int node = t >> 4;
    if (node >= N_NODES) return;
    int lane = t & 15;

    float4 acc = g_z0[(size_t)node * C4 + lane];   // self term
    acc = hop_sum(g_z0, node, lane, acc);
    float dv = g_dinv[node];
    float s = dv * dv;
    acc.x *= s; acc.y *= s; acc.z *= s; acc.w *= s;
    g_z1[(size_t)node * C4 + lane] = acc;
}

__global__ void k_hop2(float4* __restrict__ out,
                       const float4* __restrict__ bias) {  // out = dinv*(z1+sum) + b
    int t = blockIdx.x * blockDim.x + threadIdx.x;
    int node = t >> 4;
    if (node >= N_NODES) return;
    int lane = t & 15;

    float4 acc = g_z1[(size_t)node * C4 + lane];   // self term
    acc = hop_sum(g_z1, node, lane, acc);
    float dv = g_dinv[node];
    float4 bb = __ldg(&bias[lane]);
    out[(size_t)node * C4 + lane] =
        make_float4(fmaf(acc.x, dv, bb.x), fmaf(acc.y, dv, bb.y),
                    fmaf(acc.z, dv, bb.z), fmaf(acc.w, dv, bb.w));
}

// ---------------- launch ----------------
extern "C" void kernel_launch(void* const* d_in, const int* in_sizes, int n_in,
                              void* d_out, int out_size) {
    const float* X  = (const float*)d_in[0];
    const void*  EI =               d_in[1];
    const float* W  = (const float*)d_in[2];
    const float* B  = (const float*)d_in[3];

    const int TB = 256;

    k_init <<<1, 64>>>((const int*)EI);
    k_cw   <<<GE_BLKS + WS_BLKS, TB>>>(EI, W);
    k_scanA<<<NBLK, 256>>>();
    k_mf   <<<MM_BLKS + FI_BLKS, 128>>>(EI, X);

    int gH = (N_NODES * 16 + TB - 1) / TB;   // 16 lanes per node
    k_hop1<<<gH, TB>>>();
    k_hop2<<<gH, TB>>>((float4*)d_out, (const float4*)B);
}

// round 13
// speedup vs baseline: 1.2393x; 1.0681x over previous
#include <cuda_runtime.h>
#include <stdint.h>

#define N_NODES   100000
#define N_EDGES   1600000
#define N_FEAT    128
#define N_CLASSES 64
#define C4        (N_CLASSES / 4)         // 16 float4 per node row
#define NBLK      ((N_NODES + 255) / 256) // 391 scan blocks
#define GE_BLKS   ((N_EDGES + 255) / 256) // 6250 (256-thr count blocks)
#define WS_BLKS   ((N_FEAT * N_CLASSES + 255) / 256) // 32 W-pack blocks
#define MM_BLKS   ((N_NODES + 63) / 64)   // 1563 GEMM blocks (64 nodes each)
#define FI_BLKS   ((N_EDGES + 127) / 128) // 12500 fill blocks (128 thr)

// ---------------- scratch (device globals; no allocation) ----------------
__device__ int    g_cnt [N_NODES];
__device__ int    g_deg [N_NODES];
__device__ int    g_off [N_NODES];
__device__ int    g_cur [N_NODES];
__device__ int    g_total;
__device__ float  g_dinv[N_NODES];
__device__ int    g_csr [N_EDGES];            // src only (weights via z-substitution)
// W in B-fragment order: [kt(16)][nt(8)][lane(32)] x float4{bh0,bh1,bl0,bl1}
__device__ __align__(16) float g_wf[16 * 8 * 32 * 4];
__device__ float4 g_z0  [N_NODES * C4];       // dinv * (X @ W^T)
__device__ float4 g_z1  [N_NODES * C4];
__device__ int    g_is64;

// ---------------- helpers ----------------
__device__ __forceinline__ uint32_t f2tf32(float x) {
    uint32_t r;
    asm("cvt.rna.tf32.f32 %0, %1;" : "=r"(r) : "f"(x));
    return r;
}
__device__ __forceinline__ void mma_tf32(float* c,
                                         uint32_t a0, uint32_t a1, uint32_t a2, uint32_t a3,
                                         uint32_t b0, uint32_t b1) {
    asm volatile(
        "mma.sync.aligned.m16n8k8.row.col.f32.tf32.tf32.f32 "
        "{%0,%1,%2,%3}, {%4,%5,%6,%7}, {%8,%9}, {%0,%1,%2,%3};"
        : "+f"(c[0]), "+f"(c[1]), "+f"(c[2]), "+f"(c[3])
        : "r"(a0), "r"(a1), "r"(a2), "r"(a3), "r"(b0), "r"(b1));
}

// ---------------- init: dtype detect + total reset ----------------
__global__ void k_init(const int* __restrict__ ei32) {
    if (threadIdx.x == 0) {
        g_total = 0;
        int ok = 1;
        #pragma unroll
        for (int j = 1; j < 64; j += 2) ok &= (ei32[j] == 0);
        g_is64 = ok;
    }
}

// ---------------- count + W split/pack (stitched grid) ----------------
__global__ void k_cw(const void* __restrict__ eiv, const float* __restrict__ W) {
    if (blockIdx.x < GE_BLKS) {
        int e = blockIdx.x * blockDim.x + threadIdx.x;
        if (e >= N_EDGES) return;
        int c;
        if (g_is64) c = (int)((const long long*)eiv)[N_EDGES + e];
        else        c =       ((const int*)      eiv)[N_EDGES + e];
        atomicAdd(&g_cnt[c], 1);
    } else {
        int o = (blockIdx.x - GE_BLKS) * blockDim.x + threadIdx.x;
        if (o >= N_FEAT * N_CLASSES) return;
        int c = o >> 7, k = o & 127;
        float w = W[o];
        uint32_t hi = f2tf32(w);
        uint32_t lo = f2tf32(w - __uint_as_float(hi));
        int kt = k >> 3, kc = k & 7, nt = c >> 3;
        int lane = (c & 7) * 4 + (kc & 3);
        int slot = kc >> 2;                       // 0 -> b0, 1 -> b1
        int idx  = ((kt * 8 + nt) * 32 + lane) * 4;
        g_wf[idx + slot]     = __uint_as_float(hi);
        g_wf[idx + 2 + slot] = __uint_as_float(lo);
    }
}

// ---------------- offset allocation + dinv + deg snapshot + count reset ----------
__global__ void k_scanA() {
    __shared__ int s[256];
    __shared__ int base;
    int i = blockIdx.x * 256 + threadIdx.x;
    int v = (i < N_NODES) ? g_cnt[i] : 0;
    if (i < N_NODES) {
        g_cnt[i] = 0;                        // reset for next replay
        g_deg[i] = v;
        g_dinv[i] = rsqrtf((float)v + 1.0f); // +1 self-loop
    }
    int sum = v;
    s[threadIdx.x] = sum;
    __syncthreads();
    #pragma unroll
    for (int off = 1; off < 256; off <<= 1) {
        int t2 = (threadIdx.x >= off) ? s[threadIdx.x - off] : 0;
        __syncthreads();
        sum += t2;
        s[threadIdx.x] = sum;
        __syncthreads();
    }
    if (threadIdx.x == 255) base = atomicAdd(&g_total, sum);
    __syncthreads();
    if (i < N_NODES) {
        int o = base + sum - v;
        g_off[i] = o;
        g_cur[i] = o;
    }
}

// ---------------- stitched: 3xTF32 mma GEMM + CSR fill ----------------
// GEMM: z0 = dinv * (X @ W^T). Warp = 16 nodes x 64 classes; block = 64 nodes.
// Inner loop is pass-major: 8 independent MMAs between reuses of any acc[nt],
// hiding HMMA latency; all 8 B fragments LDG'd up front for MLP.
__global__ __launch_bounds__(128) void k_mf(const void* __restrict__ eiv,
                                            const float* __restrict__ X) {
    __shared__ float Xs[64][132];
    if (blockIdx.x < MM_BLKS) {
        const int tid = threadIdx.x, w = tid >> 5, lane = tid & 31;
        const int node0 = blockIdx.x * 64;

        for (int i = tid; i < 64 * 32; i += 128) {
            int n = i >> 5, q = i & 31;
            int node = node0 + n;
            float4 v = (node < N_NODES)
                     ? __ldg((const float4*)(X + (size_t)node * N_FEAT) + q)
                     : make_float4(0.f, 0.f, 0.f, 0.f);
            *(float4*)&Xs[n][q * 4] = v;
        }
        __syncthreads();

        float acc[8][4];
        #pragma unroll
        for (int nt = 0; nt < 8; nt++)
            #pragma unroll
            for (int i = 0; i < 4; i++) acc[nt][i] = 0.f;

        const int r0 = w * 16 + (lane >> 2);     // rows r0, r0+8 of block tile
        const int kc = lane & 3;
        const float4* wf = (const float4*)g_wf;

        #pragma unroll
        for (int kt = 0; kt < 16; kt++) {
            // hoist all 8 B fragments (independent LDG.128s, deep MLP)
            float4 b[8];
            #pragma unroll
            for (int nt = 0; nt < 8; nt++)
                b[nt] = __ldg(&wf[(kt * 8 + nt) * 32 + lane]);

            float x0 = Xs[r0][kt * 8 + kc];
            float x1 = Xs[r0 + 8][kt * 8 + kc];
            float x2 = Xs[r0][kt * 8 + kc + 4];
            float x3 = Xs[r0 + 8][kt * 8 + kc + 4];
            uint32_t ah0 = f2tf32(x0), ah1 = f2tf32(x1);
            uint32_t ah2 = f2tf32(x2), ah3 = f2tf32(x3);
            uint32_t al0 = f2tf32(x0 - __uint_as_float(ah0));
            uint32_t al1 = f2tf32(x1 - __uint_as_float(ah1));
            uint32_t al2 = f2tf32(x2 - __uint_as_float(ah2));
            uint32_t al3 = f2tf32(x3 - __uint_as_float(ah3));

            // pass-major sweeps: consecutive same-acc MMAs are 8 apart
            #pragma unroll
            for (int nt = 0; nt < 8; nt++)
                mma_tf32(acc[nt], ah0, ah1, ah2, ah3,
                         __float_as_uint(b[nt].x), __float_as_uint(b[nt].y));
            #pragma unroll
            for (int nt = 0; nt < 8; nt++)
                mma_tf32(acc[nt], ah0, ah1, ah2, ah3,
                         __float_as_uint(b[nt].z), __float_as_uint(b[nt].w));
            #pragma unroll
            for (int nt = 0; nt < 8; nt++)
                mma_tf32(acc[nt], al0, al1, al2, al3,
                         __float_as_uint(b[nt].x), __float_as_uint(b[nt].y));
        }

        // epilogue: scale by dinv, store. c0,c1 -> row r0; c2,c3 -> row r0+8.
        int nodeA = node0 + r0, nodeB = nodeA + 8;
        float dA = (nodeA < N_NODES) ? g_dinv[nodeA] : 0.f;
        float dB = (nodeB < N_NODES) ? g_dinv[nodeB] : 0.f;
        float* z = (float*)g_z0;
        #pragma unroll
        for (int nt = 0; nt < 8; nt++) {
            int col = nt * 8 + kc * 2;
            if (nodeA < N_NODES)
                *(float2*)&z[(size_t)nodeA * N_CLASSES + col] =
                    make_float2(acc[nt][0] * dA, acc[nt][1] * dA);
            if (nodeB < N_NODES)
                *(float2*)&z[(size_t)nodeB * N_CLASSES + col] =
                    make_float2(acc[nt][2] * dB, acc[nt][3] * dB);
        }
    } else {
        // CSR fill: src index only
        int e = (blockIdx.x - MM_BLKS) * 128 + threadIdx.x;
        if (e >= N_EDGES) return;
        int r, c;
        if (g_is64) {
            const long long* p = (const long long*)eiv;
            r = (int)p[e]; c = (int)p[N_EDGES + e];
        } else {
            const int* p = (const int*)eiv;
            r = p[e];      c = p[N_EDGES + e];
        }
        int pos = atomicAdd(&g_cur[c], 1);
        if (pos >= 0 && pos < N_EDGES)
            g_csr[pos] = r;
    }
}

// ---------------- propagation hops: 16 lanes/node, float4, z-form ----------------
__device__ __forceinline__ float4 hop_sum(const float4* __restrict__ in,
                                          int node, int lane, float4 acc) {
    int j   = g_off[node];
    int end = j + g_deg[node];
    if (end > N_EDGES) end = N_EDGES;   // defensive

    for (; j + 3 < end; j += 4) {
        int s0 = __ldg(&g_csr[j]);
        int s1 = __ldg(&g_csr[j + 1]);
        int s2 = __ldg(&g_csr[j + 2]);
        int s3 = __ldg(&g_csr[j + 3]);
        float4 u0 = __ldg(&in[(size_t)s0 * C4 + lane]);
        float4 u1 = __ldg(&in[(size_t)s1 * C4 + lane]);
        float4 u2 = __ldg(&in[(size_t)s2 * C4 + lane]);
        float4 u3 = __ldg(&in[(size_t)s3 * C4 + lane]);
        acc.x += u0.x + u1.x; acc.y += u0.y + u1.y;
        acc.z += u0.z + u1.z; acc.w += u0.w + u1.w;
        acc.x += u2.x + u3.x; acc.y += u2.y + u3.y;
        acc.z += u2.z + u3.z; acc.w += u2.w + u3.w;
    }
    for (; j < end; j++) {
        int s0 = __ldg(&g_csr[j]);
        float4 u0 = __ldg(&in[(size_t)s0 * C4 + lane]);
        acc.x += u0.x; acc.y += u0.y; acc.z += u0.z; acc.w += u0.w;
    }
    return acc;
}

__global__ void k_hop1() {   // g_z1 = dinv^2 * (z0 + sum z0[src])
    int t = blockIdx.x * blockDim.x + threadIdx.x;
    int node = t >> 4;
    if (node >= N_NODES) return;
    int lane = t & 15;

    float4 acc = g_z0[(size_t)node * C4 + lane];   // self term
    acc = hop_sum(g_z0, node, lane, acc);
    float dv = g_dinv[node];
    float s = dv * dv;
    acc.x *= s; acc.y *= s; acc.z *= s; acc.w *= s;
    g_z1[(size_t)node * C4 + lane] = acc;
}

__global__ void k_hop2(float4* __restrict__ out,
                       const float4* __restrict__ bias) {  // out = dinv*(z1+sum) + b
    int t = blockIdx.x * blockDim.x + threadIdx.x;
    int node = t >> 4;
    if (node >= N_NODES) return;
    int lane = t & 15;

    float4 acc = g_z1[(size_t)node * C4 + lane];   // self term
    acc = hop_sum(g_z1, node, lane, acc);
    float dv = g_dinv[node];
    float4 bb = __ldg(&bias[lane]);
    out[(size_t)node * C4 + lane] =
        make_float4(fmaf(acc.x, dv, bb.x), fmaf(acc.y, dv, bb.y),
                    fmaf(acc.z, dv, bb.z), fmaf(acc.w, dv, bb.w));
}

// ---------------- launch ----------------
extern "C" void kernel_launch(void* const* d_in, const int* in_sizes, int n_in,
                              void* d_out, int out_size) {
    const float* X  = (const float*)d_in[0];
    const void*  EI =               d_in[1];
    const float* W  = (const float*)d_in[2];
    const float* B  = (const float*)d_in[3];

    const int TB = 256;

    k_init <<<1, 64>>>((const int*)EI);
    k_cw   <<<GE_BLKS + WS_BLKS, TB>>>(EI, W);
    k_scanA<<<NBLK, 256>>>();
    k_mf   <<<MM_BLKS + FI_BLKS, 128>>>(EI, X);

    int gH = (N_NODES * 16 + TB - 1) / TB;   // 16 lanes per node
    k_hop1<<<gH, TB>>>();
    k_hop2<<<gH, TB>>>((float4*)d_out, (const float4*)B);
}

// round 15
// speedup vs baseline: 1.3086x; 1.0559x over previous
#include <cuda_runtime.h>
#include <stdint.h>

#define N_NODES   100000
#define N_EDGES   1600000
#define N_FEAT    128
#define N_CLASSES 64
#define C4        (N_CLASSES / 4)         // 16 float4 per node row
#define NBLK      ((N_NODES + 255) / 256) // 391 scan blocks
#define GE_BLKS   ((N_EDGES + 255) / 256) // 6250 (256-thr blocks)
#define WS_BLKS   ((N_FEAT * N_CLASSES + 255) / 256) // 32 W-pack blocks
#define GM_BLKS   ((N_NODES + 127) / 128) // 782 GEMM blocks (128 nodes each)

// ---------------- scratch (device globals; no allocation) ----------------
__device__ int    g_cnt [N_NODES];
__device__ int    g_deg [N_NODES];
__device__ int    g_off [N_NODES];
__device__ int    g_cur [N_NODES];
__device__ int    g_total;
__device__ float  g_dinv[N_NODES];
__device__ int    g_csr [N_EDGES];            // src only (weights via z-substitution)
// W in B-fragment order: [kt(16)][nt(8)][lane(32)] x float4{bh0,bh1,bl0,bl1}
__device__ __align__(16) float g_wf[16 * 8 * 32 * 4];
__device__ float4 g_z0  [N_NODES * C4];       // dinv * (X @ W^T)
__device__ float4 g_z1  [N_NODES * C4];
__device__ int    g_is64;

// ---------------- helpers ----------------
__device__ __forceinline__ uint32_t f2tf32(float x) {
    uint32_t r;
    asm("cvt.rna.tf32.f32 %0, %1;" : "=r"(r) : "f"(x));
    return r;
}
__device__ __forceinline__ void mma_tf32(float* c,
                                         uint32_t a0, uint32_t a1, uint32_t a2, uint32_t a3,
                                         uint32_t b0, uint32_t b1) {
    asm volatile(
        "mma.sync.aligned.m16n8k8.row.col.f32.tf32.tf32.f32 "
        "{%0,%1,%2,%3}, {%4,%5,%6,%7}, {%8,%9}, {%0,%1,%2,%3};"
        : "+f"(c[0]), "+f"(c[1]), "+f"(c[2]), "+f"(c[3])
        : "r"(a0), "r"(a1), "r"(a2), "r"(a3), "r"(b0), "r"(b1));
}

// ---------------- init: dtype detect + total reset ----------------
__global__ void k_init(const int* __restrict__ ei32) {
    if (threadIdx.x == 0) {
        g_total = 0;
        int ok = 1;
        #pragma unroll
        for (int j = 1; j < 64; j += 2) ok &= (ei32[j] == 0);
        g_is64 = ok;
    }
}

// ---------------- count + W split/pack (stitched grid) ----------------
__global__ void k_cw(const void* __restrict__ eiv, const float* __restrict__ W) {
    if (blockIdx.x < GE_BLKS) {
        int e = blockIdx.x * blockDim.x + threadIdx.x;
        if (e >= N_EDGES) return;
        int c;
        if (g_is64) c = (int)((const long long*)eiv)[N_EDGES + e];
        else        c =       ((const int*)      eiv)[N_EDGES + e];
        atomicAdd(&g_cnt[c], 1);
    } else {
        int o = (blockIdx.x - GE_BLKS) * blockDim.x + threadIdx.x;
        if (o >= N_FEAT * N_CLASSES) return;
        int c = o >> 7, k = o & 127;
        float w = W[o];
        uint32_t hi = f2tf32(w);
        uint32_t lo = f2tf32(w - __uint_as_float(hi));
        int kt = k >> 3, kc = k & 7, nt = c >> 3;
        int lane = (c & 7) * 4 + (kc & 3);
        int slot = kc >> 2;                       // 0 -> b0, 1 -> b1
        int idx  = ((kt * 8 + nt) * 32 + lane) * 4;
        g_wf[idx + slot]     = __uint_as_float(hi);
        g_wf[idx + 2 + slot] = __uint_as_float(lo);
    }
}

// ---------------- offset allocation + dinv + deg snapshot + count reset ----------
__global__ void k_scanA() {
    __shared__ int s[256];
    __shared__ int base;
    int i = blockIdx.x * 256 + threadIdx.x;
    int v = (i < N_NODES) ? g_cnt[i] : 0;
    if (i < N_NODES) {
        g_cnt[i] = 0;                        // reset for next replay
        g_deg[i] = v;
        g_dinv[i] = rsqrtf((float)v + 1.0f); // +1 self-loop
    }
    int sum = v;
    s[threadIdx.x] = sum;
    __syncthreads();
    #pragma unroll
    for (int off = 1; off < 256; off <<= 1) {
        int t2 = (threadIdx.x >= off) ? s[threadIdx.x - off] : 0;
        __syncthreads();
        sum += t2;
        s[threadIdx.x] = sum;
        __syncthreads();
    }
    if (threadIdx.x == 255) base = atomicAdd(&g_total, sum);
    __syncthreads();
    if (i < N_NODES) {
        int o = base + sum - v;
        g_off[i] = o;
        g_cur[i] = o;
    }
}

// ---------------- CSR fill (standalone: low regs, no smem, high occ) ----------
__global__ void k_fill(const void* __restrict__ eiv) {
    int e = blockIdx.x * blockDim.x + threadIdx.x;
    if (e >= N_EDGES) return;
    int r, c;
    if (g_is64) {
        const long long* p = (const long long*)eiv;
        r = (int)p[e]; c = (int)p[N_EDGES + e];
    } else {
        const int* p = (const int*)eiv;
        r = p[e];      c = p[N_EDGES + e];
    }
    int pos = atomicAdd(&g_cur[c], 1);
    if (pos >= 0 && pos < N_EDGES)
        g_csr[pos] = r;
}

// ---------------- 3xTF32 mma GEMM: z0 = dinv * (X @ W^T) ----------------
// Warp = 32 rows x 64 cols; block = 4 warps = 128 nodes. No smem: A fragments
// straight from global (each X element consumed by exactly one thread; L1
// catches the 4x line reuse across adjacent kt). MMAs issued pass-major in
// nt-groups of 4 -> accumulator reuse distance 8.
__global__ __launch_bounds__(128) void k_gm(const float* __restrict__ X) {
    const int tid = threadIdx.x, w = tid >> 5, lane = tid & 31;
    const int node0 = blockIdx.x * 128;
    const int r0 = w * 32 + (lane >> 2);       // rows r0, +8, +16, +24
    const int kc = lane & 3;

    // clamped row pointers (stores are bounds-guarded; loads stay in-bounds)
    const float* xr0 = X + (size_t)min(node0 + r0,      N_NODES - 1) * N_FEAT;
    const float* xr1 = X + (size_t)min(node0 + r0 + 8,  N_NODES - 1) * N_FEAT;
    const float* xr2 = X + (size_t)min(node0 + r0 + 16, N_NODES - 1) * N_FEAT;
    const float* xr3 = X + (size_t)min(node0 + r0 + 24, N_NODES - 1) * N_FEAT;

    float acc0[8][4], acc1[8][4];
    #pragma unroll
    for (int nt = 0; nt < 8; nt++)
        #pragma unroll
        for (int i = 0; i < 4; i++) { acc0[nt][i] = 0.f; acc1[nt][i] = 0.f; }

    const float4* wf = (const float4*)g_wf;

    #pragma unroll
    for (int kt = 0; kt < 16; kt++) {
        int c0 = kt * 8 + kc, c1 = c0 + 4;
        // tile0 rows (r0, r0+8), tile1 rows (r0+16, r0+24)
        float x0 = __ldg(xr0 + c0), x1 = __ldg(xr1 + c0);
        float x2 = __ldg(xr0 + c1), x3 = __ldg(xr1 + c1);
        float x4 = __ldg(xr2 + c0), x5 = __ldg(xr3 + c0);
        float x6 = __ldg(xr2 + c1), x7 = __ldg(xr3 + c1);

        uint32_t h0 = f2tf32(x0), h1 = f2tf32(x1), h2 = f2tf32(x2), h3 = f2tf32(x3);
        uint32_t h4 = f2tf32(x4), h5 = f2tf32(x5), h6 = f2tf32(x6), h7 = f2tf32(x7);
        uint32_t l0 = f2tf32(x0 - __uint_as_float(h0));
        uint32_t l1 = f2tf32(x1 - __uint_as_float(h1));
        uint32_t l2 = f2tf32(x2 - __uint_as_float(h2));
        uint32_t l3 = f2tf32(x3 - __uint_as_float(h3));
        uint32_t l4 = f2tf32(x4 - __uint_as_float(h4));
        uint32_t l5 = f2tf32(x5 - __uint_as_float(h5));
        uint32_t l6 = f2tf32(x6 - __uint_as_float(h6));
        uint32_t l7 = f2tf32(x7 - __uint_as_float(h7));

        #pragma unroll
        for (int g = 0; g < 2; g++) {
            float4 b[4];
            #pragma unroll
            for (int q = 0; q < 4; q++)
                b[q] = __ldg(&wf[(kt * 8 + g * 4 + q) * 32 + lane]);

            // pass hh
            #pragma unroll
            for (int q = 0; q < 4; q++) {
                uint32_t bh0 = __float_as_uint(b[q].x), bh1 = __float_as_uint(b[q].y);
                mma_tf32(acc0[g * 4 + q], h0, h1, h2, h3, bh0, bh1);
                mma_tf32(acc1[g * 4 + q], h4, h5, h6, h7, bh0, bh1);
            }
            // pass hl
            #pragma unroll
            for (int q = 0; q < 4; q++) {
                uint32_t bl0 = __float_as_uint(b[q].z), bl1 = __float_as_uint(b[q].w);
                mma_tf32(acc0[g * 4 + q], h0, h1, h2, h3, bl0, bl1);
                mma_tf32(acc1[g * 4 + q], h4, h5, h6, h7, bl0, bl1);
            }
            // pass lh
            #pragma unroll
            for (int q = 0; q < 4; q++) {
                uint32_t bh0 = __float_as_uint(b[q].x), bh1 = __float_as_uint(b[q].y);
                mma_tf32(acc0[g * 4 + q], l0, l1, l2, l3, bh0, bh1);
                mma_tf32(acc1[g * 4 + q], l4, l5, l6, l7, bh0, bh1);
            }
        }
    }

    // epilogue: scale by dinv, store. Per tile: c0,c1 -> row; c2,c3 -> row+8.
    float* z = (float*)g_z0;
    int nA = node0 + r0;
    float dA = (nA      < N_NODES) ? g_dinv[nA]      : 0.f;
    float dB = (nA + 8  < N_NODES) ? g_dinv[nA + 8]  : 0.f;
    float dC = (nA + 16 < N_NODES) ? g_dinv[nA + 16] : 0.f;
    float dD = (nA + 24 < N_NODES) ? g_dinv[nA + 24] : 0.f;
    #pragma unroll
    for (int nt = 0; nt < 8; nt++) {
        int col = nt * 8 + kc * 2;
        if (nA < N_NODES)
            *(float2*)&z[(size_t)nA * N_CLASSES + col] =
                make_float2(acc0[nt][0] * dA, acc0[nt][1] * dA);
        if (nA + 8 < N_NODES)
            *(float2*)&z[(size_t)(nA + 8) * N_CLASSES + col] =
                make_float2(acc0[nt][2] * dB, acc0[nt][3] * dB);
        if (nA + 16 < N_NODES)
            *(float2*)&z[(size_t)(nA + 16) * N_CLASSES + col] =
                make_float2(acc1[nt][0] * dC, acc1[nt][1] * dC);
        if (nA + 24 < N_NODES)
            *(float2*)&z[(size_t)(nA + 24) * N_CLASSES + col] =
                make_float2(acc1[nt][2] * dD, acc1[nt][3] * dD);
    }
}

// ---------------- propagation hops: 16 lanes/node, float4, z-form ----------------
__device__ __forceinline__ float4 hop_sum(const float4* __restrict__ in,
                                          int node, int lane, float4 acc) {
    int j   = g_off[node];
    int end = j + g_deg[node];
    if (end > N_EDGES) end = N_EDGES;   // defensive

    for (; j + 3 < end; j += 4) {
        int s0 = __ldg(&g_csr[j]);
        int s1 = __ldg(&g_csr[j + 1]);
        int s2 = __ldg(&g_csr[j + 2]);
        int s3 = __ldg(&g_csr[j + 3]);
        float4 u0 = __ldg(&in[(size_t)s0 * C4 + lane]);
        float4 u1 = __ldg(&in[(size_t)s1 * C4 + lane]);
        float4 u2 = __ldg(&in[(size_t)s2 * C4 + lane]);
        float4 u3 = __ldg(&in[(size_t)s3 * C4 + lane]);
        acc.x += u0.x + u1.x; acc.y += u0.y + u1.y;
        acc.z += u0.z + u1.z; acc.w += u0.w + u1.w;
        acc.x += u2.x + u3.x; acc.y += u2.y + u3.y;
        acc.z += u2.z + u3.z; acc.w += u2.w + u3.w;
    }
    for (; j < end; j++) {
        int s0 = __ldg(&g_csr[j]);
        float4 u0 = __ldg(&in[(size_t)s0 * C4 + lane]);
        acc.x += u0.x; acc.y += u0.y; acc.z += u0.z; acc.w += u0.w;
    }
    return acc;
}

__global__ void k_hop1() {   // g_z1 = dinv^2 * (z0 + sum z0[src])
    int t = blockIdx.x * blockDim.x + threadIdx.x;
    int node = t >> 4;
    if (node >= N_NODES) return;
    int lane = t & 15;

    float4 acc = g_z0[(size_t)node * C4 + lane];   // self term
    acc = hop_sum(g_z0, node, lane, acc);
    float dv = g_dinv[node];
    float s = dv * dv;
    acc.x *= s; acc.y *= s; acc.z *= s; acc.w *= s;
    g_z1[(size_t)node * C4 + lane] = acc;
}

__global__ void k_hop2(float4* __restrict__ out,
                       const float4* __restrict__ bias) {  // out = dinv*(z1+sum) + b
    int t = blockIdx.x * blockDim.x + threadIdx.x;
    int node = t >> 4;
    if (node >= N_NODES) return;
    int lane = t & 15;

    float4 acc = g_z1[(size_t)node * C4 + lane];   // self term
    acc = hop_sum(g_z1, node, lane, acc);
    float dv = g_dinv[node];
    float4 bb = __ldg(&bias[lane]);
    out[(size_t)node * C4 + lane] =
        make_float4(fmaf(acc.x, dv, bb.x), fmaf(acc.y, dv, bb.y),
                    fmaf(acc.z, dv, bb.z), fmaf(acc.w, dv, bb.w));
}

// ---------------- launch ----------------
extern "C" void kernel_launch(void* const* d_in, const int* in_sizes, int n_in,
                              void* d_out, int out_size) {
    const float* X  = (const float*)d_in[0];
    const void*  EI =               d_in[1];
    const float* W  = (const float*)d_in[2];
    const float* B  = (const float*)d_in[3];

    const int TB = 256;

    k_init <<<1, 64>>>((const int*)EI);
    k_cw   <<<GE_BLKS + WS_BLKS, TB>>>(EI, W);
    k_scanA<<<NBLK, 256>>>();
    k_fill <<<GE_BLKS, TB>>>(EI);
    k_gm   <<<GM_BLKS, 128>>>(X);

    int gH = (N_NODES * 16 + TB - 1) / TB;   // 16 lanes per node
    k_hop1<<<gH, TB>>>();
    k_hop2<<<gH, TB>>>((float4*)d_out, (const float4*)B);
}

// round 16
// speedup vs baseline: 1.6250x; 1.2418x over previous
#include <cuda_runtime.h>
#include <cuda_fp16.h>
#include <stdint.h>

#define N_NODES   100000
#define N_EDGES   1600000
#define N_FEAT    128
#define N_CLASSES 64
#define NBLK      ((N_NODES + 255) / 256) // 391 scan blocks
#define GE_BLKS   ((N_EDGES + 255) / 256) // 6250 (256-thr blocks)
#define WS_BLKS   ((N_FEAT * N_CLASSES + 255) / 256) // 32 W-pack blocks
#define GM_BLKS   ((N_NODES + 127) / 128) // 782 GEMM blocks (128 nodes each)

// ---------------- scratch (device globals; no allocation) ----------------
__device__ int    g_cnt [N_NODES];
__device__ int    g_deg [N_NODES];
__device__ int    g_off [N_NODES];
__device__ int    g_cur [N_NODES];
__device__ int    g_total;
__device__ float  g_dinv[N_NODES];
__device__ int    g_csr [N_EDGES];            // src only (weights via z-substitution)
// W in B-fragment order: [kt(16)][nt(8)][lane(32)] x float4{bh0,bh1,bl0,bl1}
__device__ __align__(16) float g_wf[16 * 8 * 32 * 4];
__device__ uint2  g_h0 [N_NODES * 16];        // z0 as fp16: 64 halves/node, 4/lane
__device__ uint2  g_h1 [N_NODES * 16];        // z1 as fp16
__device__ int    g_is64;

// ---------------- helpers ----------------
__device__ __forceinline__ uint32_t f2tf32(float x) {
    uint32_t r;
    asm("cvt.rna.tf32.f32 %0, %1;" : "=r"(r) : "f"(x));
    return r;
}
__device__ __forceinline__ void mma_tf32(float* c,
                                         uint32_t a0, uint32_t a1, uint32_t a2, uint32_t a3,
                                         uint32_t b0, uint32_t b1) {
    asm volatile(
        "mma.sync.aligned.m16n8k8.row.col.f32.tf32.tf32.f32 "
        "{%0,%1,%2,%3}, {%4,%5,%6,%7}, {%8,%9}, {%0,%1,%2,%3};"
        : "+f"(c[0]), "+f"(c[1]), "+f"(c[2]), "+f"(c[3])
        : "r"(a0), "r"(a1), "r"(a2), "r"(a3), "r"(b0), "r"(b1));
}
// accumulate 4 halves (uint2) into 4 floats
__device__ __forceinline__ void acc_h4(float4& a, uint2 p) {
    float2 f0 = __half22float2(*(__half2*)&p.x);
    float2 f1 = __half22float2(*(__half2*)&p.y);
    a.x += f0.x; a.y += f0.y; a.z += f1.x; a.w += f1.y;
}

// ---------------- init: dtype detect + total reset ----------------
__global__ void k_init(const int* __restrict__ ei32) {
    if (threadIdx.x == 0) {
        g_total = 0;
        int ok = 1;
        #pragma unroll
        for (int j = 1; j < 64; j += 2) ok &= (ei32[j] == 0);
        g_is64 = ok;
    }
}

// ---------------- count + W split/pack (stitched grid) ----------------
__global__ void k_cw(const void* __restrict__ eiv, const float* __restrict__ W) {
    if (blockIdx.x < GE_BLKS) {
        int e = blockIdx.x * blockDim.x + threadIdx.x;
        if (e >= N_EDGES) return;
        int c;
        if (g_is64) c = (int)((const long long*)eiv)[N_EDGES + e];
        else        c =       ((const int*)      eiv)[N_EDGES + e];
        atomicAdd(&g_cnt[c], 1);
    } else {
        int o = (blockIdx.x - GE_BLKS) * blockDim.x + threadIdx.x;
        if (o >= N_FEAT * N_CLASSES) return;
        int c = o >> 7, k = o & 127;
        float w = W[o];
        uint32_t hi = f2tf32(w);
        uint32_t lo = f2tf32(w - __uint_as_float(hi));
        int kt = k >> 3, kc = k & 7, nt = c >> 3;
        int lane = (c & 7) * 4 + (kc & 3);
        int slot = kc >> 2;                       // 0 -> b0, 1 -> b1
        int idx  = ((kt * 8 + nt) * 32 + lane) * 4;
        g_wf[idx + slot]     = __uint_as_float(hi);
        g_wf[idx + 2 + slot] = __uint_as_float(lo);
    }
}

// ---------------- offset allocation + dinv + deg snapshot + count reset ----------
__global__ void k_scanA() {
    __shared__ int s[256];
    __shared__ int base;
    int i = blockIdx.x * 256 + threadIdx.x;
    int v = (i < N_NODES) ? g_cnt[i] : 0;
    if (i < N_NODES) {
        g_cnt[i] = 0;                        // reset for next replay
        g_deg[i] = v;
        g_dinv[i] = rsqrtf((float)v + 1.0f); // +1 self-loop
    }
    int sum = v;
    s[threadIdx.x] = sum;
    __syncthreads();
    #pragma unroll
    for (int off = 1; off < 256; off <<= 1) {
        int t2 = (threadIdx.x >= off) ? s[threadIdx.x - off] : 0;
        __syncthreads();
        sum += t2;
        s[threadIdx.x] = sum;
        __syncthreads();
    }
    if (threadIdx.x == 255) base = atomicAdd(&g_total, sum);
    __syncthreads();
    if (i < N_NODES) {
        int o = base + sum - v;
        g_off[i] = o;
        g_cur[i] = o;
    }
}

// ---------------- CSR fill (standalone: low regs, no smem, high occ) ----------
__global__ void k_fill(const void* __restrict__ eiv) {
    int e = blockIdx.x * blockDim.x + threadIdx.x;
    if (e >= N_EDGES) return;
    int r, c;
    if (g_is64) {
        const long long* p = (const long long*)eiv;
        r = (int)p[e]; c = (int)p[N_EDGES + e];
    } else {
        const int* p = (const int*)eiv;
        r = p[e];      c = p[N_EDGES + e];
    }
    int pos = atomicAdd(&g_cur[c], 1);
    if (pos >= 0 && pos < N_EDGES)
        g_csr[pos] = r;
}

// ---------------- 3xTF32 mma GEMM: z0(fp16) = dinv * (X @ W^T) ----------------
// Warp = 32 rows x 64 cols; block = 4 warps = 128 nodes. No smem.
__global__ __launch_bounds__(128) void k_gm(const float* __restrict__ X) {
    const int tid = threadIdx.x, w = tid >> 5, lane = tid & 31;
    const int node0 = blockIdx.x * 128;
    const int r0 = w * 32 + (lane >> 2);       // rows r0, +8, +16, +24
    const int kc = lane & 3;

    const float* xr0 = X + (size_t)min(node0 + r0,      N_NODES - 1) * N_FEAT;
    const float* xr1 = X + (size_t)min(node0 + r0 + 8,  N_NODES - 1) * N_FEAT;
    const float* xr2 = X + (size_t)min(node0 + r0 + 16, N_NODES - 1) * N_FEAT;
    const float* xr3 = X + (size_t)min(node0 + r0 + 24, N_NODES - 1) * N_FEAT;

    float acc0[8][4], acc1[8][4];
    #pragma unroll
    for (int nt = 0; nt < 8; nt++)
        #pragma unroll
        for (int i = 0; i < 4; i++) { acc0[nt][i] = 0.f; acc1[nt][i] = 0.f; }

    const float4* wf = (const float4*)g_wf;

    #pragma unroll
    for (int kt = 0; kt < 16; kt++) {
        int c0 = kt * 8 + kc, c1 = c0 + 4;
        float x0 = __ldg(xr0 + c0), x1 = __ldg(xr1 + c0);
        float x2 = __ldg(xr0 + c1), x3 = __ldg(xr1 + c1);
        float x4 = __ldg(xr2 + c0), x5 = __ldg(xr3 + c0);
        float x6 = __ldg(xr2 + c1), x7 = __ldg(xr3 + c1);

        uint32_t h0 = f2tf32(x0), h1 = f2tf32(x1), h2 = f2tf32(x2), h3 = f2tf32(x3);
        uint32_t h4 = f2tf32(x4), h5 = f2tf32(x5), h6 = f2tf32(x6), h7 = f2tf32(x7);
        uint32_t l0 = f2tf32(x0 - __uint_as_float(h0));
        uint32_t l1 = f2tf32(x1 - __uint_as_float(h1));
        uint32_t l2 = f2tf32(x2 - __uint_as_float(h2));
        uint32_t l3 = f2tf32(x3 - __uint_as_float(h3));
        uint32_t l4 = f2tf32(x4 - __uint_as_float(h4));
        uint32_t l5 = f2tf32(x5 - __uint_as_float(h5));
        uint32_t l6 = f2tf32(x6 - __uint_as_float(h6));
        uint32_t l7 = f2tf32(x7 - __uint_as_float(h7));

        #pragma unroll
        for (int g = 0; g < 2; g++) {
            float4 b[4];
            #pragma unroll
            for (int q = 0; q < 4; q++)
                b[q] = __ldg(&wf[(kt * 8 + g * 4 + q) * 32 + lane]);

            #pragma unroll
            for (int q = 0; q < 4; q++) {
                uint32_t bh0 = __float_as_uint(b[q].x), bh1 = __float_as_uint(b[q].y);
                mma_tf32(acc0[g * 4 + q], h0, h1, h2, h3, bh0, bh1);
                mma_tf32(acc1[g * 4 + q], h4, h5, h6, h7, bh0, bh1);
            }
            #pragma unroll
            for (int q = 0; q < 4; q++) {
                uint32_t bl0 = __float_as_uint(b[q].z), bl1 = __float_as_uint(b[q].w);
                mma_tf32(acc0[g * 4 + q], h0, h1, h2, h3, bl0, bl1);
                mma_tf32(acc1[g * 4 + q], h4, h5, h6, h7, bl0, bl1);
            }
            #pragma unroll
            for (int q = 0; q < 4; q++) {
                uint32_t bh0 = __float_as_uint(b[q].x), bh1 = __float_as_uint(b[q].y);
                mma_tf32(acc0[g * 4 + q], l0, l1, l2, l3, bh0, bh1);
                mma_tf32(acc1[g * 4 + q], l4, l5, l6, l7, bh0, bh1);
            }
        }
    }

    // epilogue: scale by dinv, store fp16 pairs (cols nt*8+kc*2, +1)
    __half2* hz = (__half2*)g_h0;               // 32 half2 per node
    int nA = node0 + r0;
    float dA = (nA      < N_NODES) ? g_dinv[nA]      : 0.f;
    float dB = (nA + 8  < N_NODES) ? g_dinv[nA + 8]  : 0.f;
    float dC = (nA + 16 < N_NODES) ? g_dinv[nA + 16] : 0.f;
    float dD = (nA + 24 < N_NODES) ? g_dinv[nA + 24] : 0.f;
    #pragma unroll
    for (int nt = 0; nt < 8; nt++) {
        int h2col = nt * 4 + kc;                 // (nt*8 + kc*2)/2
        if (nA < N_NODES)
            hz[(size_t)nA * 32 + h2col] =
                __floats2half2_rn(acc0[nt][0] * dA, acc0[nt][1] * dA);
        if (nA + 8 < N_NODES)
            hz[(size_t)(nA + 8) * 32 + h2col] =
                __floats2half2_rn(acc0[nt][2] * dB, acc0[nt][3] * dB);
        if (nA + 16 < N_NODES)
            hz[(size_t)(nA + 16) * 32 + h2col] =
                __floats2half2_rn(acc1[nt][0] * dC, acc1[nt][1] * dC);
        if (nA + 24 < N_NODES)
            hz[(size_t)(nA + 24) * 32 + h2col] =
                __floats2half2_rn(acc1[nt][2] * dD, acc1[nt][3] * dD);
    }
}

// ---------------- propagation hops: 16 lanes/node, 4 halves/lane ----------------
__device__ __forceinline__ float4 hop_sum_h(const uint2* __restrict__ in,
                                            int node, int lane, float4 acc) {
    int j   = g_off[node];
    int end = j + g_deg[node];
    if (end > N_EDGES) end = N_EDGES;   // defensive

    for (; j + 3 < end; j += 4) {
        int s0 = __ldg(&g_csr[j]);
        int s1 = __ldg(&g_csr[j + 1]);
        int s2 = __ldg(&g_csr[j + 2]);
        int s3 = __ldg(&g_csr[j + 3]);
        uint2 u0 = __ldg(&in[(size_t)s0 * 16 + lane]);
        uint2 u1 = __ldg(&in[(size_t)s1 * 16 + lane]);
        uint2 u2 = __ldg(&in[(size_t)s2 * 16 + lane]);
        uint2 u3 = __ldg(&in[(size_t)s3 * 16 + lane]);
        acc_h4(acc, u0); acc_h4(acc, u1); acc_h4(acc, u2); acc_h4(acc, u3);
    }
    for (; j < end; j++) {
        int s0 = __ldg(&g_csr[j]);
        uint2 u0 = __ldg(&in[(size_t)s0 * 16 + lane]);
        acc_h4(acc, u0);
    }
    return acc;
}

__global__ void k_hop1() {   // g_h1 = fp16( dinv^2 * (z0 + sum z0[src]) )
    int t = blockIdx.x * blockDim.x + threadIdx.x;
    int node = t >> 4;
    if (node >= N_NODES) return;
    int lane = t & 15;

    float4 acc = make_float4(0.f, 0.f, 0.f, 0.f);
    acc_h4(acc, g_h0[(size_t)node * 16 + lane]);   // self term
    acc = hop_sum_h(g_h0, node, lane, acc);
    float dv = g_dinv[node];
    float s = dv * dv;
    uint2 o;
    __half2 p0 = __floats2half2_rn(acc.x * s, acc.y * s);
    __half2 p1 = __floats2half2_rn(acc.z * s, acc.w * s);
    o.x = *(uint32_t*)&p0; o.y = *(uint32_t*)&p1;
    g_h1[(size_t)node * 16 + lane] = o;
}

__global__ void k_hop2(float4* __restrict__ out,
                       const float4* __restrict__ bias) {  // out = dinv*(z1+sum) + b
    int t = blockIdx.x * blockDim.x + threadIdx.x;
    int node = t >> 4;
    if (node >= N_NODES) return;
    int lane = t & 15;

    float4 acc = make_float4(0.f, 0.f, 0.f, 0.f);
    acc_h4(acc, g_h1[(size_t)node * 16 + lane]);   // self term
    acc = hop_sum_h(g_h1, node, lane, acc);
    float dv = g_dinv[node];
    float4 bb = __ldg(&bias[lane]);
    out[(size_t)node * 16 + lane] =
        make_float4(fmaf(acc.x, dv, bb.x), fmaf(acc.y, dv, bb.y),
                    fmaf(acc.z, dv, bb.z), fmaf(acc.w, dv, bb.w));
}

// ---------------- launch ----------------
extern "C" void kernel_launch(void* const* d_in, const int* in_sizes, int n_in,
                              void* d_out, int out_size) {
    const float* X  = (const float*)d_in[0];
    const void*  EI =               d_in[1];
    const float* W  = (const float*)d_in[2];
    const float* B  = (const float*)d_in[3];

    const int TB = 256;

    // side stream + events, created once (first call runs outside capture)
    static cudaStream_t s1 = nullptr;
    static cudaEvent_t evA = nullptr, evB = nullptr;
    if (!s1) {
        cudaStreamCreateWithFlags(&s1, cudaStreamNonBlocking);
        cudaEventCreateWithFlags(&evA, cudaEventDisableTiming);
        cudaEventCreateWithFlags(&evB, cudaEventDisableTiming);
    }

    k_init <<<1, 64>>>((const int*)EI);
    k_cw   <<<GE_BLKS + WS_BLKS, TB>>>(EI, W);
    k_scanA<<<NBLK, 256>>>();

    // fork: k_gm on s1, k_fill on main stream (independent of each other)
    cudaEventRecord(evA, 0);
    cudaStreamWaitEvent(s1, evA, 0);
    k_gm   <<<GM_BLKS, 128, 0, s1>>>(X);
    k_fill <<<GE_BLKS, TB>>>(EI);
    cudaEventRecord(evB, s1);
    cudaStreamWaitEvent(0, evB, 0);   // join

    int gH = (N_NODES * 16 + TB - 1) / TB;   // 16 lanes per node
    k_hop1<<<gH, TB>>>();
    k_hop2<<<gH, TB>>>((float4*)d_out, (const float4*)B);
}